// round 1
// baseline (speedup 1.0000x reference)
#include <cuda_runtime.h>
#include <math.h>

// ---------------------------------------------------------------------------
// GAT_652835029007 — sparse dependency-pruned evaluation.
// Output = h2[node N-1] only => prune to the ~0.01% of the graph that matters.
// ---------------------------------------------------------------------------

#define NNODE 20001
#define LASTN 20000
#define INF   256
#define HID   128
#define NH    4
#define HD    (NH * HID)   // 512
#define NB    2
#define NE    500000
#define BMW   626          // ceil(20001/32)

#define MAX_D2 8192
#define MAX_E1 262144
#define MAX_X1 16384
#define MAX_S1 8192
#define MAX_MATCH 2048

#define INV_SCALE (1.0f / 22.627416997969522f)   // 1/sqrt(512)

// ------------------------------- scratch -----------------------------------
__device__ int      g_d2_cnt[NB];
__device__ int      g_d2_dst[NB][MAX_D2];
__device__ unsigned g_s1_bm[NB][BMW];
__device__ unsigned g_x1_bm[NB][BMW];
__device__ int      g_s1_cnt[NB];
__device__ int      g_x1_cnt[NB];
__device__ int      g_s1_list[NB][MAX_S1];
__device__ int      g_x1_list[NB][MAX_X1];
__device__ int      g_s1_idx[NB][NNODE];
__device__ int      g_x1_idx[NB][NNODE];
__device__ int      g_e1_cnt[NB];
__device__ int      g_e1_src[NB][MAX_E1];
__device__ int      g_e1_dst[NB][MAX_E1];
__device__ float    g_x1v[NB][MAX_X1][HD];
__device__ float    g_ps1[NB][MAX_X1][NH];
__device__ float    g_pd1[NB][MAX_X1][NH];
__device__ float    g_hln[NB][MAX_S1][HD];
__device__ float    g_x2v[NB][MAX_S1][HD];
__device__ float    g_ps2[NB][MAX_S1][NH];
__device__ float    g_pd2[NB][MAX_S1][NH];

// ------------------------------- helpers -----------------------------------
__device__ __forceinline__ float warpsum(float v) {
#pragma unroll
    for (int off = 16; off; off >>= 1)
        v += __shfl_down_sync(0xffffffffu, v, off);
    return v;
}

__device__ __forceinline__ float blockreduce256(float v, float* sred) {
    int t = threadIdx.x;
    sred[t] = v; __syncthreads();
#pragma unroll
    for (int s = 128; s > 0; s >>= 1) {
        if (t < s) sred[t] += sred[t + s];
        __syncthreads();
    }
    float r = sred[0]; __syncthreads();
    return r;
}

__device__ __forceinline__ float blockreduce128(float v, float* sred) {
    int t = threadIdx.x;
    sred[t] = v; __syncthreads();
#pragma unroll
    for (int s = 64; s > 0; s >>= 1) {
        if (t < s) sred[t] += sred[t + s];
        __syncthreads();
    }
    float r = sred[0]; __syncthreads();
    return r;
}

__device__ __forceinline__ void x1_add(int b, int node) {
    unsigned m = 1u << (node & 31);
    unsigned old = atomicOr(&g_x1_bm[b][node >> 5], m);
    if (!(old & m)) {
        int p = atomicAdd(&g_x1_cnt[b], 1);
        if (p < MAX_X1) { g_x1_list[b][p] = node; g_x1_idx[b][node] = p; }
    }
}

// ------------------------------- kernels -----------------------------------

// K0: reset counters + bitmaps, seed node LASTN into S1 and X1.
__global__ void k0_init() {
    int t = threadIdx.x;
    for (int b = 0; b < NB; b++)
        for (int i = t; i < BMW; i += blockDim.x) {
            g_s1_bm[b][i] = 0u; g_x1_bm[b][i] = 0u;
        }
    __syncthreads();
    if (t == 0) {
        for (int b = 0; b < NB; b++) {
            g_d2_cnt[b] = 0; g_e1_cnt[b] = 0;
            g_s1_cnt[b] = 1; g_x1_cnt[b] = 1;
            g_s1_list[b][0] = LASTN; g_s1_idx[b][LASTN] = 0;
            g_x1_list[b][0] = LASTN; g_x1_idx[b][LASTN] = 0;
            g_s1_bm[b][LASTN >> 5] |= 1u << (LASTN & 31);
            g_x1_bm[b][LASTN >> 5] |= 1u << (LASTN & 31);
        }
    }
}

// K1: scan edge_out for src == LASTN -> D2 list; dsts join S1 (and X1).
__global__ void k1_scan_out(const int* __restrict__ eo) {
    int b = blockIdx.y;
    long i = (long)blockIdx.x * blockDim.x + threadIdx.x;
    if (i >= NE) return;
    const int* base = eo + (long)b * 2 * NE;
    int src = base[i];
    if (src == LASTN) {
        int dst = base[NE + i];
        int p = atomicAdd(&g_d2_cnt[b], 1);
        if (p < MAX_D2) g_d2_dst[b][p] = dst;
        unsigned m = 1u << (dst & 31);
        unsigned old = atomicOr(&g_s1_bm[b][dst >> 5], m);
        if (!(old & m)) {
            int q = atomicAdd(&g_s1_cnt[b], 1);
            if (q < MAX_S1) { g_s1_list[b][q] = dst; g_s1_idx[b][dst] = q; }
            x1_add(b, dst);
        }
    }
}

// K2: scan edge_in for src in S1 -> E1 edge list; dsts join X1.
__global__ void k2_scan_in(const int* __restrict__ ei) {
    int b = blockIdx.y;
    long i = (long)blockIdx.x * blockDim.x + threadIdx.x;
    if (i >= NE) return;
    const int* base = ei + (long)b * 2 * NE;
    int src = base[i];
    if ((g_s1_bm[b][src >> 5] >> (src & 31)) & 1u) {
        int dst = base[NE + i];
        int p = atomicAdd(&g_e1_cnt[b], 1);
        if (p < MAX_E1) { g_e1_src[b][p] = src; g_e1_dst[b][p] = dst; }
        x1_add(b, dst);
    }
}

// K3: x1[n] = embed[n] @ W1[h].T + b1  for all X1 nodes.
// Block = 256 thr (8 warps). Warp -> one output (h,o); 16 nodes per chunk via
// shared embed tile. grid = (64, 64, NB), chunk-looped.
__global__ void k3_x1(const float* __restrict__ embed,
                      const float* __restrict__ W1,
                      const float* __restrict__ b1) {
    int b = blockIdx.z;
    int cnt = min(g_x1_cnt[b], MAX_X1);
    int t = threadIdx.x;
    int w = t >> 5, lane = t & 31;
    int out = blockIdx.y * 8 + w;             // 0..511
    __shared__ float semb[16 * 256];
    __shared__ int   snode[16];

    const float4* wr = (const float4*)(W1 + (size_t)out * INF);
    float4 w4a = wr[lane];
    float4 w4b = wr[lane + 32];
    float bias = b1[out];
    const float4* sv = (const float4*)semb;

    for (int chunk = blockIdx.x; chunk * 16 < cnt; chunk += gridDim.x) {
        __syncthreads();
        if (t < 16) {
            int idx = chunk * 16 + t;
            snode[t] = (idx < cnt) ? g_x1_list[b][idx] : -1;
        }
        __syncthreads();
        for (int u = t; u < 16 * 64; u += 256) {
            int j = u >> 6, k4 = u & 63;
            int nd = snode[j];
            float4 v = make_float4(0.f, 0.f, 0.f, 0.f);
            if (nd >= 0) v = ((const float4*)embed)[(size_t)nd * 64 + k4];
            ((float4*)semb)[u] = v;
        }
        __syncthreads();
        for (int j = 0; j < 16; j++) {
            int idx = chunk * 16 + j;
            if (idx >= cnt) break;
            float4 ea = sv[j * 64 + lane];
            float4 eb = sv[j * 64 + 32 + lane];
            float p = w4a.x * ea.x + w4a.y * ea.y + w4a.z * ea.z + w4a.w * ea.w
                    + w4b.x * eb.x + w4b.y * eb.y + w4b.z * eb.z + w4b.w * eb.w;
            p = warpsum(p);
            if (lane == 0) g_x1v[b][idx][out] = p + bias;
        }
    }
}

// K3b: ps1/pd1 = x1 . a1_src / a1_dst. Block 128 = 4 warps (one head each).
__global__ void k3b_psd1(const float* __restrict__ a1) {
    int b = blockIdx.y;
    int cnt = min(g_x1_cnt[b], MAX_X1);
    int t = threadIdx.x;
    int h = t >> 5, lane = t & 31;
    const float4* av = (const float4*)(a1 + h * 256);
    float4 s4 = av[lane];        // a1[h, 0:128]
    float4 d4 = av[32 + lane];   // a1[h, 128:256]
    for (int p = blockIdx.x; p < cnt; p += gridDim.x) {
        float4 x4 = ((const float4*)(g_x1v[b][p] + h * HID))[lane];
        float ps = x4.x * s4.x + x4.y * s4.y + x4.z * s4.z + x4.w * s4.w;
        float pd = x4.x * d4.x + x4.y * d4.y + x4.z * d4.z + x4.w * d4.w;
        ps = warpsum(ps); pd = warpsum(pd);
        if (lane == 0) { g_ps1[b][p][h] = ps; g_pd1[b][p][h] = pd; }
    }
}

// K4: per S1-node layer-1 aggregation + LayerNorm(ddof=1) + ELU -> g_hln.
__global__ void k4_agg(const float* __restrict__ g1, const float* __restrict__ bn1) {
    int b = blockIdx.y;
    int scnt = min(g_s1_cnt[b], MAX_S1);
    int ecnt = min(g_e1_cnt[b], MAX_E1);
    int t = threadIdx.x;
    __shared__ float s_hp[HD];
    __shared__ float s_rs[NH];
    __shared__ int   s_mcnt;
    __shared__ int   s_md[MAX_MATCH];
    __shared__ float s_me[MAX_MATCH][NH];
    __shared__ float s_red[256];

    for (int p = blockIdx.x; p < scnt; p += gridDim.x) {
        __syncthreads();
        for (int u = t; u < HD; u += 256) s_hp[u] = 0.f;
        if (t < NH) s_rs[t] = 0.f;
        if (t == 0) s_mcnt = 0;
        int node = g_s1_list[b][p];
        int xn = g_x1_idx[b][node];
        float psn[NH];
#pragma unroll
        for (int h = 0; h < NH; h++) psn[h] = g_ps1[b][xn][h];
        __syncthreads();

        // phase A: collect matching edges + attention weights + rowsums
        for (int i = t; i < ecnt; i += 256) {
            if (g_e1_src[b][i] == node) {
                int d = g_e1_dst[b][i];
                int xd = g_x1_idx[b][d];
                int m = atomicAdd(&s_mcnt, 1);
                if (m < MAX_MATCH) {
                    s_md[m] = xd;
#pragma unroll
                    for (int h = 0; h < NH; h++) {
                        float s = psn[h] + g_pd1[b][xd][h];
                        float l = s > 0.f ? s : 0.2f * s;
                        float e = expf(l * INV_SCALE);
                        s_me[m][h] = e;
                        atomicAdd(&s_rs[h], e);
                    }
                }
            }
        }
        __syncthreads();

        // phase B: weighted accumulation of x1[dst] (thread owns fixed u's)
        int mc = min(s_mcnt, MAX_MATCH);
        for (int m = 0; m < mc; m++) {
            int xd = s_md[m];
            const float* xr = g_x1v[b][xd];
            for (int u = t; u < HD; u += 256)
                s_hp[u] += s_me[m][u >> 7] * xr[u];
        }
        __syncthreads();

        float rsv[NH];
#pragma unroll
        for (int h = 0; h < NH; h++) {
            float r = s_rs[h];
            rsv[h] = (r == 0.f) ? 1.f : r;
        }
        float v0 = s_hp[t] / rsv[t >> 7];
        float v1 = s_hp[t + 256] / rsv[(t + 256) >> 7];

        float mean = blockreduce256(v0 + v1, s_red) * (1.f / 512.f);
        float d0 = v0 - mean, d1 = v1 - mean;
        float var = blockreduce256(d0 * d0 + d1 * d1, s_red) * (1.f / 511.f);
        float inv = 1.f / (sqrtf(var) + 1e-6f);
        float y0 = g1[t] * d0 * inv + bn1[t];
        float y1 = g1[t + 256] * d1 * inv + bn1[t + 256];
        y0 = y0 > 0.f ? y0 : expf(y0) - 1.f;   // ELU
        y1 = y1 > 0.f ? y1 : expf(y1) - 1.f;
        g_hln[b][p][t] = y0;
        g_hln[b][p][t + 256] = y1;
        __syncthreads();
    }
}

// K5: x2 = hln @ W2[h].T + b2 for all S1 nodes. Warp per output, 8 nodes/chunk.
__global__ void k5_x2(const float* __restrict__ W2, const float* __restrict__ b2) {
    int b = blockIdx.z;
    int cnt = min(g_s1_cnt[b], MAX_S1);
    int t = threadIdx.x;
    int w = t >> 5, lane = t & 31;
    int out = blockIdx.y * 8 + w;
    __shared__ float sh[8 * 512];

    const float4* wr = (const float4*)(W2 + (size_t)out * HD);
    float4 w4[4];
#pragma unroll
    for (int c = 0; c < 4; c++) w4[c] = wr[lane + 32 * c];
    float bias = b2[out];

    for (int chunk = blockIdx.x; chunk * 8 < cnt; chunk += gridDim.x) {
        __syncthreads();
        for (int u = t; u < 8 * 128; u += 256) {
            int j = u >> 7, k4 = u & 127;
            int idx = chunk * 8 + j;
            float4 v = make_float4(0.f, 0.f, 0.f, 0.f);
            if (idx < cnt) v = ((const float4*)g_hln[b][idx])[k4];
            ((float4*)sh)[u] = v;
        }
        __syncthreads();
        for (int j = 0; j < 8; j++) {
            int idx = chunk * 8 + j;
            if (idx >= cnt) break;
            float p = 0.f;
#pragma unroll
            for (int c = 0; c < 4; c++) {
                float4 e = ((const float4*)sh)[j * 128 + lane + 32 * c];
                p += w4[c].x * e.x + w4[c].y * e.y + w4[c].z * e.z + w4[c].w * e.w;
            }
            p = warpsum(p);
            if (lane == 0) g_x2v[b][idx][out] = p + bias;
        }
    }
}

// K5b: ps2/pd2 = x2 . a2_src / a2_dst
__global__ void k5b_psd2(const float* __restrict__ a2) {
    int b = blockIdx.y;
    int cnt = min(g_s1_cnt[b], MAX_S1);
    int t = threadIdx.x;
    int h = t >> 5, lane = t & 31;
    const float4* av = (const float4*)(a2 + h * 256);
    float4 s4 = av[lane];
    float4 d4 = av[32 + lane];
    for (int p = blockIdx.x; p < cnt; p += gridDim.x) {
        float4 x4 = ((const float4*)(g_x2v[b][p] + h * HID))[lane];
        float ps = x4.x * s4.x + x4.y * s4.y + x4.z * s4.z + x4.w * s4.w;
        float pd = x4.x * d4.x + x4.y * d4.y + x4.z * d4.z + x4.w * d4.w;
        ps = warpsum(ps); pd = warpsum(pd);
        if (lane == 0) { g_ps2[b][p][h] = ps; g_pd2[b][p][h] = pd; }
    }
}

// K6: layer-2 aggregation at node LASTN + mean-over-heads + LN + ReLU + proj.
__global__ void k6_final(const float* __restrict__ g2, const float* __restrict__ bn2,
                         const float* __restrict__ Vw, const float* __restrict__ Vb,
                         float* __restrict__ out) {
    int b = blockIdx.x;
    int o = threadIdx.x;   // 0..127
    __shared__ float s_red[128];
    int ec = min(g_d2_cnt[b], MAX_D2);

    float psl[NH];
#pragma unroll
    for (int h = 0; h < NH; h++) psl[h] = g_ps2[b][0][h];   // node LASTN is s1 idx 0

    float hp[NH] = {0.f, 0.f, 0.f, 0.f};
    float rs[NH] = {0.f, 0.f, 0.f, 0.f};
    for (int i = 0; i < ec; i++) {
        int d = g_d2_dst[b][i];
        int pd = g_s1_idx[b][d];
#pragma unroll
        for (int h = 0; h < NH; h++) {
            float s = psl[h] + g_pd2[b][pd][h];
            float l = s > 0.f ? s : 0.2f * s;
            float e = expf(l * INV_SCALE);
            rs[h] += e;
            hp[h] += e * g_x2v[b][pd][h * HID + o];
        }
    }
    float v = 0.f;
#pragma unroll
    for (int h = 0; h < NH; h++) {
        float r = rs[h];
        r = (r == 0.f) ? 1.f : r;
        v += hp[h] / r;
    }
    v *= 0.25f;   // mean over heads

    float mean = blockreduce128(v, s_red) * (1.f / 128.f);
    float dv = v - mean;
    float var = blockreduce128(dv * dv, s_red) * (1.f / 127.f);
    float inv = 1.f / (sqrtf(var) + 1e-6f);
    float y = g2[o] * dv * inv + bn2[o];
    y = y > 0.f ? y : 0.f;   // ReLU

    float c0 = blockreduce128(y * Vw[o], s_red);
    float c1 = blockreduce128(y * Vw[HID + o], s_red);
    if (o == 0) {
        out[b * 2 + 0] = c0 + Vb[0];
        out[b * 2 + 1] = c1 + Vb[1];
    }
}

// ------------------------------- launcher ----------------------------------
extern "C" void kernel_launch(void* const* d_in, const int* in_sizes, int n_in,
                              void* d_out, int out_size) {
    const int*   edge_in  = (const int*)d_in[0];
    const int*   edge_out = (const int*)d_in[1];
    const float* embed    = (const float*)d_in[2];
    const float* W1       = (const float*)d_in[3];
    const float* b1       = (const float*)d_in[4];
    const float* a1       = (const float*)d_in[5];
    const float* g1       = (const float*)d_in[6];
    const float* bn1      = (const float*)d_in[7];
    const float* W2       = (const float*)d_in[8];
    const float* b2       = (const float*)d_in[9];
    const float* a2       = (const float*)d_in[10];
    const float* g2       = (const float*)d_in[11];
    const float* bn2      = (const float*)d_in[12];
    const float* Vw       = (const float*)d_in[13];
    const float* Vb       = (const float*)d_in[14];
    float* out = (float*)d_out;

    k0_init<<<1, 256>>>();
    dim3 gscan((NE + 255) / 256, NB);
    k1_scan_out<<<gscan, 256>>>(edge_out);
    k2_scan_in<<<gscan, 256>>>(edge_in);
    k3_x1<<<dim3(64, 64, NB), 256>>>(embed, W1, b1);
    k3b_psd1<<<dim3(256, NB), 128>>>(a1);
    k4_agg<<<dim3(64, NB), 256>>>(g1, bn1);
    k5_x2<<<dim3(32, 64, NB), 256>>>(W2, b2);
    k5b_psd2<<<dim3(64, NB), 128>>>(a2);
    k6_final<<<NB, 128>>>(g2, bn2, Vw, Vb, out);
}